// round 16
// baseline (speedup 1.0000x reference)
#include <cuda_runtime.h>
#include <math.h>
#include <stdint.h>

#define B_ 4
#define L_ 2048
#define C_ 1024
#define H_ 16
#define D_ 64
#define M_ (B_ * L_)   // 8192 rows

// Scratch buffers (static device globals; no runtime allocation allowed)
__device__ float g_qkv[(size_t)M_ * 3 * C_];   // [8192, 3072]
__device__ float g_h[(size_t)M_ * C_];         // [8192, 1024]

// ---------------------------------------------------------------------------
// helpers: tf32 convert + m16n8k8 tf32 mma + cp.async
// ---------------------------------------------------------------------------
__device__ __forceinline__ uint32_t f2tf(float f) {
    uint32_t r;
    asm("cvt.rna.tf32.f32 %0, %1;" : "=r"(r) : "f"(f));
    return r;
}
__device__ __forceinline__ float f2tf_f(float f) {
    return __uint_as_float(f2tf(f));
}

__device__ __forceinline__ void mma_tf32(float c[4],
    uint32_t a0, uint32_t a1, uint32_t a2, uint32_t a3,
    uint32_t b0, uint32_t b1)
{
    asm volatile(
        "mma.sync.aligned.m16n8k8.row.col.f32.tf32.tf32.f32 "
        "{%0,%1,%2,%3}, {%4,%5,%6,%7}, {%8,%9}, {%0,%1,%2,%3};"
        : "+f"(c[0]), "+f"(c[1]), "+f"(c[2]), "+f"(c[3])
        : "r"(a0), "r"(a1), "r"(a2), "r"(a3), "r"(b0), "r"(b1));
}

__device__ __forceinline__ void cp_async16(uint32_t smem_addr, const void* gptr) {
    asm volatile("cp.async.cg.shared.global [%0], [%1], 16;"
                 :: "r"(smem_addr), "l"(gptr));
}
__device__ __forceinline__ void cp_commit() {
    asm volatile("cp.async.commit_group;");
}
__device__ __forceinline__ void cp_wait_all() {
    asm volatile("cp.async.wait_group 0;");
}

// ---------------------------------------------------------------------------
// TF32 tensor-core SGEMM — round-11 mainloop VERBATIM (proven 558us; LDG
// path keeps L1 reuse of shared B tiles).  Epilogue optionally fuses the
// per-head RMS norm (round-13 proven) so Q/K/V land tf32-rounded for the
// attention kernel's cp.async consumer.
// 128x128 tile, BK=16, 256 threads = 8 warps (4Mx2N), warp tile 32x64.
// ---------------------------------------------------------------------------
#define GAP 20
#define GBP 136

__global__ __launch_bounds__(256) void gemm_tc_kernel(
    const float* __restrict__ A, const float* __restrict__ Bm,
    const float* __restrict__ bias, float* __restrict__ Cm,
    int M, int N, int K, int fuse,
    const float* __restrict__ qg, const float* __restrict__ kg)
{
    __shared__ uint32_t As[128 * GAP];
    __shared__ uint32_t Bs[16 * GBP];

    const int tid  = threadIdx.x;
    const int warp = tid >> 5;
    const int lane = tid & 31;
    const int gid  = lane >> 2;
    const int t4   = lane & 3;

    const int wm = warp >> 1;
    const int wn = warp & 1;
    const int m0 = wm * 32;
    const int n0 = wn * 64;

    const int row0 = blockIdx.y * 128;
    const int col0 = blockIdx.x * 128;

    const int a_row = tid >> 1;
    const int a_k   = (tid & 1) * 8;
    const int b_row = tid >> 4;
    const int b_col = (tid & 15) * 8;

    float acc[2][8][4];
#pragma unroll
    for (int mt = 0; mt < 2; mt++)
#pragma unroll
        for (int nt = 0; nt < 8; nt++)
#pragma unroll
            for (int i = 0; i < 4; i++) acc[mt][nt][i] = 0.0f;

    const float* Aptr = A + (size_t)(row0 + a_row) * K;

    for (int k0 = 0; k0 < K; k0 += 16) {
        float4 av0 = *(const float4*)(Aptr + k0 + a_k);
        float4 av1 = *(const float4*)(Aptr + k0 + a_k + 4);
        {
            uint4 u0 = make_uint4(f2tf(av0.x), f2tf(av0.y), f2tf(av0.z), f2tf(av0.w));
            uint4 u1 = make_uint4(f2tf(av1.x), f2tf(av1.y), f2tf(av1.z), f2tf(av1.w));
            *(uint4*)&As[a_row * GAP + a_k]     = u0;
            *(uint4*)&As[a_row * GAP + a_k + 4] = u1;
        }
        float4 bv0 = *(const float4*)(Bm + (size_t)(k0 + b_row) * N + col0 + b_col);
        float4 bv1 = *(const float4*)(Bm + (size_t)(k0 + b_row) * N + col0 + b_col + 4);
        {
            uint4 u0 = make_uint4(f2tf(bv0.x), f2tf(bv0.y), f2tf(bv0.z), f2tf(bv0.w));
            uint4 u1 = make_uint4(f2tf(bv1.x), f2tf(bv1.y), f2tf(bv1.z), f2tf(bv1.w));
            *(uint4*)&Bs[b_row * GBP + b_col]     = u0;
            *(uint4*)&Bs[b_row * GBP + b_col + 4] = u1;
        }
        __syncthreads();

#pragma unroll
        for (int ks = 0; ks < 16; ks += 8) {
            uint32_t af[2][4];
#pragma unroll
            for (int mt = 0; mt < 2; mt++) {
                const int mbase = m0 + mt * 16;
                af[mt][0] = As[(mbase + gid)     * GAP + ks + t4];
                af[mt][1] = As[(mbase + gid + 8) * GAP + ks + t4];
                af[mt][2] = As[(mbase + gid)     * GAP + ks + t4 + 4];
                af[mt][3] = As[(mbase + gid + 8) * GAP + ks + t4 + 4];
            }
#pragma unroll
            for (int nt = 0; nt < 8; nt++) {
                uint32_t b0 = Bs[(ks + t4)     * GBP + n0 + nt * 8 + gid];
                uint32_t b1 = Bs[(ks + t4 + 4) * GBP + n0 + nt * 8 + gid];
                mma_tf32(acc[0][nt], af[0][0], af[0][1], af[0][2], af[0][3], b0, b1);
                mma_tf32(acc[1][nt], af[1][0], af[1][1], af[1][2], af[1][3], b0, b1);
            }
        }
        __syncthreads();
    }

    // ---- epilogue (round-13 proven fused RMS variant) ----
    const int gc0  = col0 + n0;          // 64-aligned; head inside warp half
    const int part = gc0 >> 10;          // 0=Q 1=K 2=V (fuse mode)
    const int hidx = (gc0 & 1023) >> 6;

#pragma unroll
    for (int mt = 0; mt < 2; mt++) {
        const int r0 = row0 + m0 + mt * 16 + gid;
        float v[8][4];
#pragma unroll
        for (int nt = 0; nt < 8; nt++) {
            const int c = gc0 + nt * 8 + t4 * 2;
            const float bx = bias[c], by = bias[c + 1];
            v[nt][0] = acc[mt][nt][0] + bx;
            v[nt][1] = acc[mt][nt][1] + by;
            v[nt][2] = acc[mt][nt][2] + bx;
            v[nt][3] = acc[mt][nt][3] + by;
        }

        if (fuse) {
            if (part == 2) {
                // V: round to tf32
#pragma unroll
                for (int nt = 0; nt < 8; nt++) {
                    const int c = gc0 + nt * 8 + t4 * 2;
                    *(float2*)(Cm + (size_t)r0 * N + c) =
                        make_float2(f2tf_f(v[nt][0]), f2tf_f(v[nt][1]));
                    *(float2*)(Cm + (size_t)(r0 + 8) * N + c) =
                        make_float2(f2tf_f(v[nt][2]), f2tf_f(v[nt][3]));
                }
            } else {
                // Q/K: per-head RMS norm (row slice of 64 = 4 t4-lanes)
                float ss0 = 0.0f, ss1 = 0.0f;
#pragma unroll
                for (int nt = 0; nt < 8; nt++) {
                    ss0 += v[nt][0] * v[nt][0] + v[nt][1] * v[nt][1];
                    ss1 += v[nt][2] * v[nt][2] + v[nt][3] * v[nt][3];
                }
#pragma unroll
                for (int msk = 1; msk <= 2; msk <<= 1) {
                    ss0 += __shfl_xor_sync(0xffffffffu, ss0, msk);
                    ss1 += __shfl_xor_sync(0xffffffffu, ss1, msk);
                }
                const float s0 = 8.0f / fmaxf(sqrtf(ss0), 1e-12f);
                const float s1 = 8.0f / fmaxf(sqrtf(ss1), 1e-12f);
                const float* gm = part ? kg : qg;
#pragma unroll
                for (int nt = 0; nt < 8; nt++) {
                    const int ch = nt * 8 + t4 * 2;
                    const float gx = gm[hidx * 64 + ch];
                    const float gy = gm[hidx * 64 + ch + 1];
                    const int c = gc0 + ch;
                    *(float2*)(Cm + (size_t)r0 * N + c) =
                        make_float2(f2tf_f(v[nt][0] * s0 * gx), f2tf_f(v[nt][1] * s0 * gy));
                    *(float2*)(Cm + (size_t)(r0 + 8) * N + c) =
                        make_float2(f2tf_f(v[nt][2] * s1 * gx), f2tf_f(v[nt][3] * s1 * gy));
                }
            }
        } else {
            // final output: plain fp32 store
#pragma unroll
            for (int nt = 0; nt < 8; nt++) {
                const int c = gc0 + nt * 8 + t4 * 2;
                *(float2*)(Cm + (size_t)r0 * N + c) = make_float2(v[nt][0], v[nt][1]);
                *(float2*)(Cm + (size_t)(r0 + 8) * N + c) = make_float2(v[nt][2], v[nt][3]);
            }
        }
    }
}

// ---------------------------------------------------------------------------
// Flash attention, TF32 mma, cp.async double-buffered K/V pipeline.
// Round-11/14 structure with the online-softmax MAX TRACKING REMOVED:
// Q/K are RMS-normalized to norm 8, so |score*scale| <= 8 and
// exp2 args are bounded by ~11.54 -> max p ~ 2980, sum <= 6.1e6: all
// comfortably in fp32.  Softmax is shift-invariant so this is exact.
// ---------------------------------------------------------------------------
#define KP2 76
#define VP2 72
#define KVW (64 * KP2 + 64 * VP2)    // 9472 words per stage
#define QPP 68
#define ATT_SMEM ((2 * KVW + 128 * QPP) * 4)   // 110592 bytes

__global__ __launch_bounds__(256, 2) void attn_tc_kernel(
    const float* __restrict__ qkv, float* __restrict__ hout)
{
    extern __shared__ uint32_t sm[];
    uint32_t* QS = sm + 2 * KVW;       // Q staging, reused as PS
    uint32_t* PS = QS;

    const uint32_t smem_u32 = (uint32_t)__cvta_generic_to_shared(sm);

    const int tid  = threadIdx.x;
    const int warp = tid >> 5;
    const int lane = tid & 31;
    const int gid  = lane >> 2;
    const int t4   = lane & 3;

    const int b  = blockIdx.z;
    const int h  = blockIdx.y;
    const int l0 = blockIdx.x * 128;

    const int qlr = tid >> 1;
    const int qlc = (tid & 1) * 32;
    const int lr = tid >> 2;            // 0..63
    const int lc = (tid & 3) * 16;      // 0,16,32,48

    const float qscale = 0.125f * 1.44269504088896340736f;  // 1/sqrt(D)*log2e

    const float* kbase = qkv + (((size_t)(b * L_ + lr) * 3 + 1) * C_) + h * D_ + lc;
    const float* vbase = qkv + (((size_t)(b * L_ + lr) * 3 + 2) * C_) + h * D_ + lc;
    const size_t rowstep = (size_t)3 * C_;

    // prologue: tile 0 -> stage 0
    {
        const uint32_t kdst = smem_u32 + (0 * KVW + lr * KP2 + lc) * 4;
        const uint32_t vdst = smem_u32 + (0 * KVW + 64 * KP2 + lr * VP2 + lc) * 4;
#pragma unroll
        for (int u = 0; u < 4; u++) {
            cp_async16(kdst + u * 16, kbase + u * 4);
            cp_async16(vdst + u * 16, vbase + u * 4);
        }
        cp_commit();
    }

    // load Q tile (pre-rounded tf32; apply qscale + re-round)
    {
        const float* src = qkv + (((size_t)(b * L_ + l0 + qlr) * 3 + 0) * C_) + h * D_;
#pragma unroll
        for (int u = 0; u < 8; u++) {
            float4 t = *(const float4*)(src + qlc + u * 4);
            uint4 uq = make_uint4(f2tf(t.x * qscale), f2tf(t.y * qscale),
                                  f2tf(t.z * qscale), f2tf(t.w * qscale));
            *(uint4*)&QS[qlr * QPP + qlc + u * 4] = uq;
        }
    }
    __syncthreads();

    uint32_t qf[8][4];
    {
        const int mbase = warp * 16;
#pragma unroll
        for (int ks = 0; ks < 8; ks++) {
            qf[ks][0] = QS[(mbase + gid)     * QPP + ks * 8 + t4];
            qf[ks][1] = QS[(mbase + gid + 8) * QPP + ks * 8 + t4];
            qf[ks][2] = QS[(mbase + gid)     * QPP + ks * 8 + t4 + 4];
            qf[ks][3] = QS[(mbase + gid + 8) * QPP + ks * 8 + t4 + 4];
        }
    }
    // First loop-top __syncthreads separates these QS reads from the first
    // PS writes (PS aliases QS).

    float o[8][4];
#pragma unroll
    for (int nt = 0; nt < 8; nt++)
#pragma unroll
        for (int i = 0; i < 4; i++) o[nt][i] = 0.0f;

    float lrow0 = 0.0f, lrow1 = 0.0f;

    for (int it = 0; it < L_ / 64; it++) {
        const int p = it & 1;
        uint32_t* Ks = sm + p * KVW;
        uint32_t* Vs = sm + p * KVW + 64 * KP2;

        cp_wait_all();
        __syncthreads();

        if (it + 1 < L_ / 64) {
            const size_t off = (size_t)(it + 1) * 64 * rowstep;
            const uint32_t s1 = (p ^ 1) * KVW;
            const uint32_t kdst = smem_u32 + (s1 + lr * KP2 + lc) * 4;
            const uint32_t vdst = smem_u32 + (s1 + 64 * KP2 + lr * VP2 + lc) * 4;
#pragma unroll
            for (int u = 0; u < 4; u++) {
                cp_async16(kdst + u * 16, kbase + off + u * 4);
                cp_async16(vdst + u * 16, vbase + off + u * 4);
            }
            cp_commit();
        }

        // S = Q K^T (exp2-domain scores; Q pre-scaled)
        float s[8][4];
#pragma unroll
        for (int nt = 0; nt < 8; nt++)
#pragma unroll
            for (int i = 0; i < 4; i++) s[nt][i] = 0.0f;

#pragma unroll
        for (int ks = 0; ks < 8; ks++) {
#pragma unroll
            for (int nt = 0; nt < 8; nt++) {
                uint32_t b0 = Ks[(nt * 8 + gid) * KP2 + ks * 8 + t4];
                uint32_t b1 = Ks[(nt * 8 + gid) * KP2 + ks * 8 + t4 + 4];
                mma_tf32(s[nt], qf[ks][0], qf[ks][1], qf[ks][2], qf[ks][3], b0, b1);
            }
        }

        // softmax numerator, NO max subtraction (bounded scores; exact
        // by shift invariance)
        const int prow0 = warp * 16 + gid;
        float rs0 = 0.0f, rs1 = 0.0f;
#pragma unroll
        for (int nt = 0; nt < 8; nt++) {
            float p0 = exp2f(s[nt][0]);
            float p1 = exp2f(s[nt][1]);
            float p2 = exp2f(s[nt][2]);
            float p3 = exp2f(s[nt][3]);
            rs0 += p0 + p1;
            rs1 += p2 + p3;
            const int cc = nt * 8 + 2 * t4;
            PS[prow0 * QPP + cc]           = f2tf(p0);
            PS[prow0 * QPP + cc + 1]       = f2tf(p1);
            PS[(prow0 + 8) * QPP + cc]     = f2tf(p2);
            PS[(prow0 + 8) * QPP + cc + 1] = f2tf(p3);
        }
#pragma unroll
        for (int msk = 1; msk <= 2; msk <<= 1) {
            rs0 += __shfl_xor_sync(0xffffffffu, rs0, msk);
            rs1 += __shfl_xor_sync(0xffffffffu, rs1, msk);
        }
        lrow0 += rs0;
        lrow1 += rs1;

        __syncwarp();   // PS rows are per-warp private

        // O += P V
#pragma unroll
        for (int ks = 0; ks < 8; ks++) {
            uint32_t pf0 = PS[(warp * 16 + gid)     * QPP + ks * 8 + t4];
            uint32_t pf1 = PS[(warp * 16 + gid + 8) * QPP + ks * 8 + t4];
            uint32_t pf2 = PS[(warp * 16 + gid)     * QPP + ks * 8 + t4 + 4];
            uint32_t pf3 = PS[(warp * 16 + gid + 8) * QPP + ks * 8 + t4 + 4];
#pragma unroll
            for (int nt = 0; nt < 8; nt++) {
                uint32_t b0 = Vs[(ks * 8 + t4)     * VP2 + nt * 8 + gid];
                uint32_t b1 = Vs[(ks * 8 + t4 + 4) * VP2 + nt * 8 + gid];
                mma_tf32(o[nt], pf0, pf1, pf2, pf3, b0, b1);
            }
        }
        __syncthreads();   // all reads of stage p done before next prefetch
    }

    // write normalized output (plain fp32; out-proj cvt's at its STS)
    const float inv0 = 1.0f / lrow0;
    const float inv1 = 1.0f / lrow1;
    const int r0 = b * L_ + l0 + warp * 16 + gid;
#pragma unroll
    for (int nt = 0; nt < 8; nt++) {
        const int c = h * D_ + nt * 8 + 2 * t4;
        *(float2*)(hout + (size_t)r0 * C_ + c) =
            make_float2(o[nt][0] * inv0, o[nt][1] * inv0);
        *(float2*)(hout + (size_t)(r0 + 8) * C_ + c) =
            make_float2(o[nt][2] * inv1, o[nt][3] * inv1);
    }
}

// ---------------------------------------------------------------------------
// kernel_launch
// ---------------------------------------------------------------------------
extern "C" void kernel_launch(void* const* d_in, const int* in_sizes, int n_in,
                              void* d_out, int out_size)
{
    const float* x     = (const float*)d_in[0];
    const float* Wqkv  = (const float*)d_in[1];
    const float* bqkv  = (const float*)d_in[2];
    const float* qg    = (const float*)d_in[3];
    const float* kg    = (const float*)d_in[4];
    const float* Wout  = (const float*)d_in[5];
    const float* bout  = (const float*)d_in[6];
    float* out = (float*)d_out;

    float *qkv, *hbuf;
    cudaGetSymbolAddress((void**)&qkv, g_qkv);
    cudaGetSymbolAddress((void**)&hbuf, g_h);

    cudaFuncSetAttribute(attn_tc_kernel,
                         cudaFuncAttributeMaxDynamicSharedMemorySize, ATT_SMEM);

    // 1) QKV projection + fused per-head RMS norm (Q,K) + tf32 rounding
    {
        dim3 grid(3 * C_ / 128, M_ / 128);
        gemm_tc_kernel<<<grid, 256>>>(x, Wqkv, bqkv, qkv,
                                      M_, 3 * C_, C_, 1, qg, kg);
    }

    // 2) Attention (cp.async pipelined, no-max softmax)
    {
        dim3 grid(L_ / 128, H_, B_);
        attn_tc_kernel<<<grid, 256, ATT_SMEM>>>(qkv, hbuf);
    }

    // 3) Output projection
    {
        dim3 grid(C_ / 128, M_ / 128);
        gemm_tc_kernel<<<grid, 256>>>(hbuf, Wout, bout, out,
                                      M_, C_, C_, 0, qg, kg);
    }
}

// round 17
// speedup vs baseline: 1.4758x; 1.4758x over previous
#include <cuda_runtime.h>
#include <math.h>
#include <stdint.h>

#define B_ 4
#define L_ 2048
#define C_ 1024
#define H_ 16
#define D_ 64
#define M_ (B_ * L_)   // 8192 rows

// Scratch buffers (static device globals; no runtime allocation allowed)
__device__ float g_qkv[(size_t)M_ * 3 * C_];   // [8192, 3072]
__device__ float g_h[(size_t)M_ * C_];         // [8192, 1024]

// ---------------------------------------------------------------------------
// helpers: tf32 convert + m16n8k8 tf32 mma + cp.async
// ---------------------------------------------------------------------------
__device__ __forceinline__ uint32_t f2tf(float f) {
    uint32_t r;
    asm("cvt.rna.tf32.f32 %0, %1;" : "=r"(r) : "f"(f));
    return r;
}

__device__ __forceinline__ float f2tf_f(float f) {
    uint32_t r = f2tf(f);
    return __uint_as_float(r);
}

__device__ __forceinline__ void mma_tf32(float c[4],
    uint32_t a0, uint32_t a1, uint32_t a2, uint32_t a3,
    uint32_t b0, uint32_t b1)
{
    asm volatile(
        "mma.sync.aligned.m16n8k8.row.col.f32.tf32.tf32.f32 "
        "{%0,%1,%2,%3}, {%4,%5,%6,%7}, {%8,%9}, {%0,%1,%2,%3};"
        : "+f"(c[0]), "+f"(c[1]), "+f"(c[2]), "+f"(c[3])
        : "r"(a0), "r"(a1), "r"(a2), "r"(a3), "r"(b0), "r"(b1));
}

__device__ __forceinline__ void cp_async16(uint32_t smem_addr, const void* gptr) {
    asm volatile("cp.async.cg.shared.global [%0], [%1], 16;"
                 :: "r"(smem_addr), "l"(gptr));
}
__device__ __forceinline__ void cp_commit() {
    asm volatile("cp.async.commit_group;");
}
__device__ __forceinline__ void cp_wait_all() {
    asm volatile("cp.async.wait_group 0;");
}

// ---------------------------------------------------------------------------
// TF32 tensor-core SGEMM — round-11 EXACT (proven: QKV 558us, regs 99).
// C[M,N] = A[M,K] @ B[K,N] + bias[N]  (row-major)
// 128x128 tile, BK=16, 256 threads = 8 warps (4Mx2N), warp tile 32x64.
// ---------------------------------------------------------------------------
#define GAP 20
#define GBP 136

__global__ __launch_bounds__(256) void gemm_tc_kernel(
    const float* __restrict__ A, const float* __restrict__ Bm,
    const float* __restrict__ bias, float* __restrict__ Cm,
    int M, int N, int K)
{
    __shared__ uint32_t As[128 * GAP];
    __shared__ uint32_t Bs[16 * GBP];

    const int tid  = threadIdx.x;
    const int warp = tid >> 5;
    const int lane = tid & 31;
    const int gid  = lane >> 2;
    const int t4   = lane & 3;

    const int wm = warp >> 1;
    const int wn = warp & 1;
    const int m0 = wm * 32;
    const int n0 = wn * 64;

    const int row0 = blockIdx.y * 128;
    const int col0 = blockIdx.x * 128;

    const int a_row = tid >> 1;
    const int a_k   = (tid & 1) * 8;
    const int b_row = tid >> 4;
    const int b_col = (tid & 15) * 8;

    float acc[2][8][4];
#pragma unroll
    for (int mt = 0; mt < 2; mt++)
#pragma unroll
        for (int nt = 0; nt < 8; nt++)
#pragma unroll
            for (int i = 0; i < 4; i++) acc[mt][nt][i] = 0.0f;

    const float* Aptr = A + (size_t)(row0 + a_row) * K;

    for (int k0 = 0; k0 < K; k0 += 16) {
        float4 av0 = *(const float4*)(Aptr + k0 + a_k);
        float4 av1 = *(const float4*)(Aptr + k0 + a_k + 4);
        {
            uint4 u0 = make_uint4(f2tf(av0.x), f2tf(av0.y), f2tf(av0.z), f2tf(av0.w));
            uint4 u1 = make_uint4(f2tf(av1.x), f2tf(av1.y), f2tf(av1.z), f2tf(av1.w));
            *(uint4*)&As[a_row * GAP + a_k]     = u0;
            *(uint4*)&As[a_row * GAP + a_k + 4] = u1;
        }
        float4 bv0 = *(const float4*)(Bm + (size_t)(k0 + b_row) * N + col0 + b_col);
        float4 bv1 = *(const float4*)(Bm + (size_t)(k0 + b_row) * N + col0 + b_col + 4);
        {
            uint4 u0 = make_uint4(f2tf(bv0.x), f2tf(bv0.y), f2tf(bv0.z), f2tf(bv0.w));
            uint4 u1 = make_uint4(f2tf(bv1.x), f2tf(bv1.y), f2tf(bv1.z), f2tf(bv1.w));
            *(uint4*)&Bs[b_row * GBP + b_col]     = u0;
            *(uint4*)&Bs[b_row * GBP + b_col + 4] = u1;
        }
        __syncthreads();

#pragma unroll
        for (int ks = 0; ks < 16; ks += 8) {
            uint32_t af[2][4];
#pragma unroll
            for (int mt = 0; mt < 2; mt++) {
                const int mbase = m0 + mt * 16;
                af[mt][0] = As[(mbase + gid)     * GAP + ks + t4];
                af[mt][1] = As[(mbase + gid + 8) * GAP + ks + t4];
                af[mt][2] = As[(mbase + gid)     * GAP + ks + t4 + 4];
                af[mt][3] = As[(mbase + gid + 8) * GAP + ks + t4 + 4];
            }
#pragma unroll
            for (int nt = 0; nt < 8; nt++) {
                uint32_t b0 = Bs[(ks + t4)     * GBP + n0 + nt * 8 + gid];
                uint32_t b1 = Bs[(ks + t4 + 4) * GBP + n0 + nt * 8 + gid];
                mma_tf32(acc[0][nt], af[0][0], af[0][1], af[0][2], af[0][3], b0, b1);
                mma_tf32(acc[1][nt], af[1][0], af[1][1], af[1][2], af[1][3], b0, b1);
            }
        }
        __syncthreads();
    }

#pragma unroll
    for (int mt = 0; mt < 2; mt++) {
        const int r0 = row0 + m0 + mt * 16 + gid;
#pragma unroll
        for (int nt = 0; nt < 8; nt++) {
            const int c = col0 + n0 + nt * 8 + t4 * 2;
            float bx = bias[c], by = bias[c + 1];
            *(float2*)(Cm + (size_t)r0 * N + c) =
                make_float2(acc[mt][nt][0] + bx, acc[mt][nt][1] + by);
            *(float2*)(Cm + (size_t)(r0 + 8) * N + c) =
                make_float2(acc[mt][nt][2] + bx, acc[mt][nt][3] + by);
        }
    }
}

// ---------------------------------------------------------------------------
// Per-head RMS norm on Q and K, in place, writing tf32-ROUNDED values so the
// attention kernel can cp.async them directly.
// ---------------------------------------------------------------------------
__global__ __launch_bounds__(256) void rmsnorm_kernel(
    float* __restrict__ qkv,
    const float* __restrict__ q_gamma, const float* __restrict__ k_gamma)
{
    const int warp = threadIdx.x >> 5;
    const int lane = threadIdx.x & 31;
    const int seg = blockIdx.x * 8 + warp;

    const int head = seg % H_;
    const int part = (seg / H_) & 1;
    const int row  = seg / (H_ * 2);

    float* ptr = qkv + ((size_t)row * 3 + part) * C_ + head * D_;
    float2 v = *(float2*)(ptr + lane * 2);
    float ss = v.x * v.x + v.y * v.y;
#pragma unroll
    for (int m = 16; m > 0; m >>= 1) ss += __shfl_xor_sync(0xffffffffu, ss, m);

    const float n = sqrtf(ss);
    const float scale = 8.0f / fmaxf(n, 1e-12f);
    const float* gamma = part ? k_gamma : q_gamma;
    float2 g = *(const float2*)(gamma + head * D_ + lane * 2);
    v.x = f2tf_f(v.x * scale * g.x);
    v.y = f2tf_f(v.y * scale * g.y);
    *(float2*)(ptr + lane * 2) = v;
}

// ---------------------------------------------------------------------------
// Round V slice of qkv to tf32 in place (producer-side convert for cp.async).
// ---------------------------------------------------------------------------
__global__ __launch_bounds__(256) void round_v_kernel(float* __restrict__ qkv)
{
    const int idx = blockIdx.x * 256 + threadIdx.x;     // float4 index
    const int row = idx >> 8;                            // C_/4 = 256 per row
    const int col = (idx & 255) * 4;
    float* p = qkv + ((size_t)row * 3 + 2) * C_ + col;
    float4 t = *(float4*)p;
    t.x = f2tf_f(t.x); t.y = f2tf_f(t.y);
    t.z = f2tf_f(t.z); t.w = f2tf_f(t.w);
    *(float4*)p = t;
}

// ---------------------------------------------------------------------------
// Flash attention, TF32 mma, cp.async double-buffered K/V pipeline.
// Round-11 structure; ONLY change: online-softmax max tracking removed.
// Q/K are RMS-normalized to norm 8 => |score*scale| <= 8, exp2 args bounded
// by 8*log2e ~ 11.54 -> max p ~ 2980, row sum <= 6.1e6: safely fp32.
// Softmax is shift-invariant, so skipping the max is mathematically exact.
// ---------------------------------------------------------------------------
#define KP2 76
#define VP2 72
#define KVW (64 * KP2 + 64 * VP2)    // 9472 words per stage
#define QPP 68
#define ATT_SMEM ((2 * KVW + 128 * QPP) * 4)   // 110592 bytes

__global__ __launch_bounds__(256, 2) void attn_tc_kernel(
    const float* __restrict__ qkv, float* __restrict__ hout)
{
    extern __shared__ uint32_t sm[];
    uint32_t* QS = sm + 2 * KVW;       // Q staging, reused as PS
    uint32_t* PS = QS;

    const uint32_t smem_u32 = (uint32_t)__cvta_generic_to_shared(sm);

    const int tid  = threadIdx.x;
    const int warp = tid >> 5;
    const int lane = tid & 31;
    const int gid  = lane >> 2;
    const int t4   = lane & 3;

    const int b  = blockIdx.z;
    const int h  = blockIdx.y;
    const int l0 = blockIdx.x * 128;

    const int qlr = tid >> 1;
    const int qlc = (tid & 1) * 32;
    const int lr = tid >> 2;            // 0..63
    const int lc = (tid & 3) * 16;      // 0,16,32,48

    const float qscale = 0.125f * 1.44269504088896340736f;  // 1/sqrt(D)*log2e

    const float* kbase = qkv + (((size_t)(b * L_ + lr) * 3 + 1) * C_) + h * D_ + lc;
    const float* vbase = qkv + (((size_t)(b * L_ + lr) * 3 + 2) * C_) + h * D_ + lc;
    const size_t rowstep = (size_t)3 * C_;

    // prologue: tile 0 -> stage 0
    {
        const uint32_t kdst = smem_u32 + (0 * KVW + lr * KP2 + lc) * 4;
        const uint32_t vdst = smem_u32 + (0 * KVW + 64 * KP2 + lr * VP2 + lc) * 4;
#pragma unroll
        for (int u = 0; u < 4; u++) {
            cp_async16(kdst + u * 16, kbase + u * 4);
            cp_async16(vdst + u * 16, vbase + u * 4);
        }
        cp_commit();
    }

    // load Q tile (pre-rounded tf32; apply qscale + re-round)
    {
        const float* src = qkv + (((size_t)(b * L_ + l0 + qlr) * 3 + 0) * C_) + h * D_;
#pragma unroll
        for (int u = 0; u < 8; u++) {
            float4 t = *(const float4*)(src + qlc + u * 4);
            uint4 uq = make_uint4(f2tf(t.x * qscale), f2tf(t.y * qscale),
                                  f2tf(t.z * qscale), f2tf(t.w * qscale));
            *(uint4*)&QS[qlr * QPP + qlc + u * 4] = uq;
        }
    }
    __syncthreads();

    uint32_t qf[8][4];
    {
        const int mbase = warp * 16;
#pragma unroll
        for (int ks = 0; ks < 8; ks++) {
            qf[ks][0] = QS[(mbase + gid)     * QPP + ks * 8 + t4];
            qf[ks][1] = QS[(mbase + gid + 8) * QPP + ks * 8 + t4];
            qf[ks][2] = QS[(mbase + gid)     * QPP + ks * 8 + t4 + 4];
            qf[ks][3] = QS[(mbase + gid + 8) * QPP + ks * 8 + t4 + 4];
        }
    }
    // First loop-top __syncthreads separates these QS reads from the first
    // PS writes (PS aliases QS).

    float o[8][4];
#pragma unroll
    for (int nt = 0; nt < 8; nt++)
#pragma unroll
        for (int i = 0; i < 4; i++) o[nt][i] = 0.0f;

    float lrow0 = 0.0f, lrow1 = 0.0f;

    for (int it = 0; it < L_ / 64; it++) {
        const int p = it & 1;
        uint32_t* Ks = sm + p * KVW;
        uint32_t* Vs = sm + p * KVW + 64 * KP2;

        cp_wait_all();
        __syncthreads();

        if (it + 1 < L_ / 64) {
            const size_t off = (size_t)(it + 1) * 64 * rowstep;
            const uint32_t s1 = (p ^ 1) * KVW;
            const uint32_t kdst = smem_u32 + (s1 + lr * KP2 + lc) * 4;
            const uint32_t vdst = smem_u32 + (s1 + 64 * KP2 + lr * VP2 + lc) * 4;
#pragma unroll
            for (int u = 0; u < 4; u++) {
                cp_async16(kdst + u * 16, kbase + off + u * 4);
                cp_async16(vdst + u * 16, vbase + off + u * 4);
            }
            cp_commit();
        }

        // S = Q K^T (scores already in exp2 domain; Q pre-scaled)
        float s[8][4];
#pragma unroll
        for (int nt = 0; nt < 8; nt++)
#pragma unroll
            for (int i = 0; i < 4; i++) s[nt][i] = 0.0f;

#pragma unroll
        for (int ks = 0; ks < 8; ks++) {
#pragma unroll
            for (int nt = 0; nt < 8; nt++) {
                uint32_t b0 = Ks[(nt * 8 + gid) * KP2 + ks * 8 + t4];
                uint32_t b1 = Ks[(nt * 8 + gid) * KP2 + ks * 8 + t4 + 4];
                mma_tf32(s[nt], qf[ks][0], qf[ks][1], qf[ks][2], qf[ks][3], b0, b1);
            }
        }

        // softmax numerator, no max subtraction (exact: bounded scores)
        const int prow0 = warp * 16 + gid;
        float rs0 = 0.0f, rs1 = 0.0f;
#pragma unroll
        for (int nt = 0; nt < 8; nt++) {
            float p0 = exp2f(s[nt][0]);
            float p1 = exp2f(s[nt][1]);
            float p2 = exp2f(s[nt][2]);
            float p3 = exp2f(s[nt][3]);
            rs0 += p0 + p1;
            rs1 += p2 + p3;
            const int cc = nt * 8 + 2 * t4;
            PS[prow0 * QPP + cc]           = f2tf(p0);
            PS[prow0 * QPP + cc + 1]       = f2tf(p1);
            PS[(prow0 + 8) * QPP + cc]     = f2tf(p2);
            PS[(prow0 + 8) * QPP + cc + 1] = f2tf(p3);
        }
#pragma unroll
        for (int msk = 1; msk <= 2; msk <<= 1) {
            rs0 += __shfl_xor_sync(0xffffffffu, rs0, msk);
            rs1 += __shfl_xor_sync(0xffffffffu, rs1, msk);
        }
        lrow0 += rs0;
        lrow1 += rs1;

        __syncwarp();   // PS rows are per-warp private

        // O += P V
#pragma unroll
        for (int ks = 0; ks < 8; ks++) {
            uint32_t pf0 = PS[(warp * 16 + gid)     * QPP + ks * 8 + t4];
            uint32_t pf1 = PS[(warp * 16 + gid + 8) * QPP + ks * 8 + t4];
            uint32_t pf2 = PS[(warp * 16 + gid)     * QPP + ks * 8 + t4 + 4];
            uint32_t pf3 = PS[(warp * 16 + gid + 8) * QPP + ks * 8 + t4 + 4];
#pragma unroll
            for (int nt = 0; nt < 8; nt++) {
                uint32_t b0 = Vs[(ks * 8 + t4)     * VP2 + nt * 8 + gid];
                uint32_t b1 = Vs[(ks * 8 + t4 + 4) * VP2 + nt * 8 + gid];
                mma_tf32(o[nt], pf0, pf1, pf2, pf3, b0, b1);
            }
        }
        __syncthreads();   // all reads of stage p done before next prefetch
    }

    // write normalized output
    const float inv0 = 1.0f / lrow0;
    const float inv1 = 1.0f / lrow1;
    const int r0 = b * L_ + l0 + warp * 16 + gid;
#pragma unroll
    for (int nt = 0; nt < 8; nt++) {
        const int c = h * D_ + nt * 8 + 2 * t4;
        *(float2*)(hout + (size_t)r0 * C_ + c) =
            make_float2(o[nt][0] * inv0, o[nt][1] * inv0);
        *(float2*)(hout + (size_t)(r0 + 8) * C_ + c) =
            make_float2(o[nt][2] * inv1, o[nt][3] * inv1);
    }
}

// ---------------------------------------------------------------------------
// kernel_launch
// ---------------------------------------------------------------------------
extern "C" void kernel_launch(void* const* d_in, const int* in_sizes, int n_in,
                              void* d_out, int out_size)
{
    const float* x     = (const float*)d_in[0];
    const float* Wqkv  = (const float*)d_in[1];
    const float* bqkv  = (const float*)d_in[2];
    const float* qg    = (const float*)d_in[3];
    const float* kg    = (const float*)d_in[4];
    const float* Wout  = (const float*)d_in[5];
    const float* bout  = (const float*)d_in[6];
    float* out = (float*)d_out;

    float *qkv, *hbuf;
    cudaGetSymbolAddress((void**)&qkv, g_qkv);
    cudaGetSymbolAddress((void**)&hbuf, g_h);

    cudaFuncSetAttribute(attn_tc_kernel,
                         cudaFuncAttributeMaxDynamicSharedMemorySize, ATT_SMEM);

    // 1) QKV projection
    {
        dim3 grid(3 * C_ / 128, M_ / 128);
        gemm_tc_kernel<<<grid, 256>>>(x, Wqkv, bqkv, qkv, M_, 3 * C_, C_);
    }

    // 2) RMS norm on Q,K (writes tf32-rounded) + round V to tf32
    {
        const int nseg = M_ * 2 * H_;
        rmsnorm_kernel<<<nseg / 8, 256>>>(qkv, qg, kg);
        round_v_kernel<<<(M_ * C_ / 4) / 256, 256>>>(qkv);
    }

    // 3) Attention (cp.async pipelined, no-max softmax)
    {
        dim3 grid(L_ / 128, H_, B_);
        attn_tc_kernel<<<grid, 256, ATT_SMEM>>>(qkv, hbuf);
    }

    // 4) Output projection
    {
        dim3 grid(C_ / 128, M_ / 128);
        gemm_tc_kernel<<<grid, 256>>>(hbuf, Wout, bout, out, M_, C_, C_);
    }
}